// round 8
// baseline (speedup 1.0000x reference)
#include <cuda_runtime.h>
#include <cstdint>

static constexpr int E_EDGES = 250000;
static constexpr int T_E     = 8;                  // edges per warp tile
static constexpr int NTILE   = E_EDGES / T_E;      // 31250 (exact)

#define SQ3f  1.7320508075688772f
#define SQ5f  2.2360679774997896f
#define SQ15f 3.8729833462074170f
#define HSQ3f 0.8660254037844386f

typedef unsigned long long u64;

__device__ __forceinline__ u64 pack2(float a, float b) {
    u64 r; asm("mov.b64 %0, {%1, %2};" : "=l"(r) : "f"(a), "f"(b)); return r;
}
__device__ __forceinline__ float2 unpk(u64 v) {
    float2 r; asm("mov.b64 {%0, %1}, %2;" : "=f"(r.x), "=f"(r.y) : "l"(v)); return r;
}
__device__ __forceinline__ void fma2(u64& d, u64 a, u64 b) {
    asm("fma.rn.f32x2 %0, %1, %2, %0;" : "+l"(d) : "l"(a), "l"(b));
}
__device__ __forceinline__ uint32_t smem_u32(const void* p) {
    uint32_t a;
    asm("{ .reg .u64 t; cvta.to.shared.u64 t, %1; cvt.u32.u64 %0, t; }" : "=r"(a) : "l"(p));
    return a;
}

// ---- shared memory layout per 256-thread block (8 warps) ----
//  WaS  : float4[64][32]                      32768 B  (block-shared)
//  WbS  : float2[64][32]                      16384 B
//  shS  : 8 warps x (8 edges x 2 float4)       2048 B
//  scr  : 8 warps x 6400 B                    51200 B
//         per warp: [0:4096)  dup-inv (8 edges x 64 u64)  ALIASES TMA slot0 [0:2304)
//                   [4096:6400) TMA slot1 (2304 B)
static constexpr int OFF_WB   = 32768;
static constexpr int OFF_SH   = 49152;
static constexpr int OFF_SCR  = 51200;
static constexpr int SCR_WARP = 6400;
static constexpr int SMEM_BYTES = OFF_SCR + 8 * SCR_WARP;   // 102400
static constexpr int EDGE_BYTES = 576 * 4;                  // 2304
static constexpr int SLOT_STRIDE = 4096;                    // slot s at scr + s*4096

__global__ void __launch_bounds__(256, 2)
sh_embed_kernel(const float* __restrict__ edge_vec,
                const float* __restrict__ inv_g,
                const float* __restrict__ Wg,
                float* __restrict__ out)
{
    extern __shared__ char smem[];
    float4* WaS = (float4*)smem;
    float2* WbS = (float2*)(smem + OFF_WB);

    const int tid  = threadIdx.x;
    const int lane = tid & 31;
    const int wid  = tid >> 5;

    float4* shS4 = (float4*)(smem + OFF_SH) + wid * (T_E * 2);
    char*   scr  = smem + OFF_SCR + wid * SCR_WARP;
    const uint32_t scrAddr = smem_u32(scr);

    // ---- repack W: lane cp owns channels c0=2cp, c1=2cp+1 ----
    // WaS[d][cp]=(W[d,6cp],W[d,6cp+3],W[d,6cp+1],W[d,6cp+4]); WbS[d][cp]=(W[d,6cp+2],W[d,6cp+5])
    for (int t = tid; t < 64 * 32; t += 256) {
        int cp = t & 31, d = t >> 5;
        const float* wr = Wg + d * 192 + cp * 6;
        WaS[t] = make_float4(wr[0], wr[3], wr[1], wr[4]);
        WbS[t] = make_float2(wr[2], wr[5]);
    }
    __syncthreads();

    const int warpsTotal = gridDim.x * 8;
    #pragma unroll 1
    for (int tile = blockIdx.x * 8 + wid; tile < NTILE; tile += warpsTotal) {
        const int eBase = tile * T_E;

        // slot0 region is about to be overwritten by dup-inv: its last TMA store
        // (edge 6 of the previous tile, second-most-recent commit) must be drained.
        if (lane == 0) asm volatile("cp.async.bulk.wait_group 1;" ::: "memory");
        __syncwarp();

        // ---- stage DUPLICATED inv tile: u64 (v,v) per (e,d); packing distributed
        //      across lanes (16 packs/thread/tile, off the hot loop) ----
        {
            const float4* src = (const float4*)(inv_g + (size_t)eBase * 64);
            ulonglong2*   dst = (ulonglong2*)scr;
            #pragma unroll
            for (int r = 0; r < 4; r++) {
                int f = r * 32 + lane;              // float4 index: e = f>>4, d-group = f&15
                float4 q = src[f];
                dst[f * 2 + 0] = make_ulonglong2(pack2(q.x, q.x), pack2(q.y, q.y));
                dst[f * 2 + 1] = make_ulonglong2(pack2(q.z, q.z), pack2(q.w, q.w));
            }
        }

        // ---- precompute SH for the 8 edges (lanes 0..7) ----
        if (lane < T_E) {
            const float* vp = edge_vec + (size_t)(eBase + lane) * 3;
            float vx = vp[0], vy = vp[1], vz = vp[2];
            float rn = rsqrtf(vx * vx + vy * vy + vz * vz);
            float x = vx * rn, y = vy * rn, z = vz * rn;
            shS4[lane * 2 + 0] = make_float4(SQ3f * x, SQ3f * y, SQ3f * z, SQ15f * x * z);
            shS4[lane * 2 + 1] = make_float4(SQ15f * x * y,
                                             SQ5f  * (y * y - 0.5f * (x * x + z * z)),
                                             SQ15f * y * z,
                                             (HSQ3f * SQ5f) * (z * z - x * x));
        }
        __syncwarp();

        // ---- GEMM: w[e, c, i] = sum_d inv[e,d] * W[d, c*3+i] ----
        u64 a0[T_E], a1[T_E], a2[T_E];
        #pragma unroll
        for (int e = 0; e < T_E; e++) { a0[e] = 0; a1[e] = 0; a2[e] = 0; }

        const ulonglong2* ivD = (const ulonglong2*)scr;
        #pragma unroll 1
        for (int d4 = 0; d4 < 16; ++d4) {
            u64 A0[4], A1[4], A2[4];
            #pragma unroll
            for (int dd = 0; dd < 4; ++dd) {
                float4 wa = WaS[(d4 * 4 + dd) * 32 + lane];
                float2 wb = WbS[(d4 * 4 + dd) * 32 + lane];
                A0[dd] = pack2(wa.x, wa.y);
                A1[dd] = pack2(wa.z, wa.w);
                A2[dd] = pack2(wb.x, wb.y);
            }
            #pragma unroll
            for (int e = 0; e < T_E; e++) {
                // 2 uniform LDS.128 broadcasts: 4 pre-duplicated inv values, no MOVs
                ulonglong2 p0 = ivD[e * 32 + d4 * 2];
                ulonglong2 p1 = ivD[e * 32 + d4 * 2 + 1];
                fma2(a0[e], p0.x, A0[0]); fma2(a1[e], p0.x, A1[0]); fma2(a2[e], p0.x, A2[0]);
                fma2(a0[e], p0.y, A0[1]); fma2(a1[e], p0.y, A1[1]); fma2(a2[e], p0.y, A2[1]);
                fma2(a0[e], p1.x, A0[2]); fma2(a1[e], p1.x, A1[2]); fma2(a2[e], p1.x, A2[2]);
                fma2(a0[e], p1.y, A0[3]); fma2(a1[e], p1.y, A1[3]); fma2(a2[e], p1.y, A2[3]);
            }
        }

        // ---- epilogue: stage each edge in FINAL layout, TMA bulk store it ----
        // lane cp's 18 floats are contiguous at float offset 18*cp.
        const int rot = lane >> 4;   // lanes 16..31 rotate write order (bank de-tie)
        #pragma unroll 1
        for (int e = 0; e < T_E; ++e) {
            // slot (e&1) reuse guard: with FIFO drain, <=1 outstanding means the
            // store 2 commits ago (same slot) is done.
            if (lane == 0) asm volatile("cp.async.bulk.wait_group 1;" ::: "memory");
            __syncwarp();

            float4 shA = shS4[e * 2 + 0];   // sh1..sh4
            float4 shB = shS4[e * 2 + 1];   // sh5..sh8
            float2 w0 = unpk(a0[e]), w1 = unpk(a1[e]), w2 = unpk(a2[e]);

            float2 pr[9];
            pr[0] = make_float2(w0.x,         shA.x * w1.x);
            pr[1] = make_float2(shA.y * w1.x, shA.z * w1.x);
            pr[2] = make_float2(shA.w * w2.x, shB.x * w2.x);
            pr[3] = make_float2(shB.y * w2.x, shB.z * w2.x);
            pr[4] = make_float2(shB.w * w2.x, w0.y);
            pr[5] = make_float2(shA.x * w1.y, shA.y * w1.y);
            pr[6] = make_float2(shA.z * w1.y, shA.w * w2.y);
            pr[7] = make_float2(shB.x * w2.y, shB.y * w2.y);
            pr[8] = make_float2(shB.z * w2.y, shB.w * w2.y);

            float2* sp = (float2*)(scr + (e & 1) * SLOT_STRIDE) + lane * 9;
            #pragma unroll
            for (int m = 0; m < 9; m++) {
                const int k = (m + 1) % 9;            // compile-time
                float2 v = rot ? pr[k] : pr[m];       // constant-indexed selects
                int    o = rot ? k     : m;
                sp[o] = v;
            }
            __syncwarp();

            if (lane == 0) {
                asm volatile("fence.proxy.async.shared::cta;" ::: "memory");
                const float* gdst = out + (size_t)(eBase + e) * 576;
                uint32_t saddr = scrAddr + (e & 1) * SLOT_STRIDE;
                asm volatile(
                    "cp.async.bulk.global.shared::cta.bulk_group [%0], [%1], %2;"
                    :: "l"(gdst), "r"(saddr), "n"(EDGE_BYTES) : "memory");
                asm volatile("cp.async.bulk.commit_group;" ::: "memory");
            }
            // no trailing sync: next iteration's wait+syncwarp orders everything
        }
    }

    // all of this warp's TMA stores must drain before smem can be released
    if (lane == 0) asm volatile("cp.async.bulk.wait_group 0;" ::: "memory");
    __syncwarp();
}

extern "C" void kernel_launch(void* const* d_in, const int* in_sizes, int n_in,
                              void* d_out, int out_size) {
    const float* edge_vec = (const float*)d_in[0];   // [E, 3]
    const float* inv      = (const float*)d_in[1];   // [E, 64]
    const float* W        = (const float*)d_in[2];   // [64, 192]
    float* out            = (float*)d_out;           // [E, 64, 9]
    (void)in_sizes; (void)n_in; (void)out_size;

    cudaFuncSetAttribute(sh_embed_kernel,
                         cudaFuncAttributeMaxDynamicSharedMemorySize, SMEM_BYTES);
    // 296 blocks (2/SM at 100KB smem), 8 warps each = 16 warps/SM
    sh_embed_kernel<<<296, 256, SMEM_BYTES>>>(edge_vec, inv, W, out);
}

// round 10
// speedup vs baseline: 1.5150x; 1.5150x over previous
#include <cuda_runtime.h>
#include <cuda_fp16.h>
#include <cstdint>

static constexpr int E_EDGES = 250000;
static constexpr int T_E     = 16;
static constexpr int NTILE   = E_EDGES / T_E;   // 15625 exact

#define SQ3f  1.7320508075688772f
#define SQ5f  2.2360679774997896f
#define SQ15f 3.8729833462074170f
#define HSQ3f 0.8660254037844386f

// ---- smem map ----
// Wh: f16[192][72] (27648 B), Wl: +27648. Per-warp region (stride 17920):
//   [0:12800)   wS f32[16][200]  (ALIASES invH f16[16][72] @0 + invL @2304)
//   [12800:13312) shs: 16 edges x 8 f32
//   [13312:17920) stage: 2 x 2304 B TMA slots
static constexpr int OFF_WL   = 27648;
static constexpr int OFF_WARP = 55296;
static constexpr int W_STRIDE = 17920;
static constexpr int R_INVL   = 2304;
static constexpr int R_SHS    = 12800;
static constexpr int R_STG    = 13312;
static constexpr int STG_SLOT = 2304;
static constexpr int SMEM_BYTES = OFF_WARP + 8 * W_STRIDE;   // 198656

__device__ __forceinline__ uint32_t smem_u32(const void* p) {
    uint32_t a;
    asm("{ .reg .u64 t; cvta.to.shared.u64 t, %1; cvt.u32.u64 %0, t; }" : "=r"(a) : "l"(p));
    return a;
}
__device__ __forceinline__ void mma16816(float& c0, float& c1, float& c2, float& c3,
                                         uint32_t a0, uint32_t a1, uint32_t a2, uint32_t a3,
                                         uint32_t b0, uint32_t b1) {
    asm volatile("mma.sync.aligned.m16n8k16.row.col.f32.f16.f16.f32 "
                 "{%0,%1,%2,%3}, {%4,%5,%6,%7}, {%8,%9}, {%0,%1,%2,%3};"
                 : "+f"(c0), "+f"(c1), "+f"(c2), "+f"(c3)
                 : "r"(a0), "r"(a1), "r"(a2), "r"(a3), "r"(b0), "r"(b1));
}

__global__ void __launch_bounds__(256, 1)
sh_embed_hmma(const float* __restrict__ edge_vec, const float* __restrict__ inv_g,
              const float* __restrict__ Wg, float* __restrict__ out)
{
    extern __shared__ char smem[];
    const int tid = threadIdx.x, lane = tid & 31, wid = tid >> 5;
    const int g = lane >> 2, t = lane & 3;     // mma quad coords

    uint32_t* WhW = (uint32_t*)smem;                 // word view, row stride 36
    uint32_t* WlW = (uint32_t*)(smem + OFF_WL);

    char* wr = smem + OFF_WARP + wid * W_STRIDE;
    uint32_t* invH = (uint32_t*)wr;                  // f16[16][72], row = 36 words
    uint32_t* invL = (uint32_t*)(wr + R_INVL);
    float*    wS   = (float*)wr;                     // f32[16][200] (aliases inv)
    float4*   shs4 = (float4*)(wr + R_SHS);
    char*     stg  = wr + R_STG;
    const uint32_t stgAddr = smem_u32(stg);

    // ---- one-time: W -> f16 hi/lo tiles, row-major [col(192)][k(64)], rows padded to 72 f16 ----
    for (int u = tid; u < 192 * 64; u += 256) {
        int col = u >> 6, d = u & 63;
        float v = Wg[d * 192 + col];
        __half h = __float2half_rn(v);
        __half l = __float2half_rn(v - __half2float(h));
        *(__half*)(smem + col * 144 + d * 2)          = h;
        *(__half*)(smem + OFF_WL + col * 144 + d * 2) = l;
    }
    __syncthreads();

    const int warpsTotal = gridDim.x * 8;
    #pragma unroll 1
    for (int tile = blockIdx.x * 8 + wid; tile < NTILE; tile += warpsTotal) {
        const int eBase = tile * T_E;
        __syncwarp();   // previous tile's wS reads done before overwriting (alias)

        // ---- stage inv tile as f16 hi/lo, rows padded to 72 f16 ----
        {
            const float4* src = (const float4*)(inv_g + (size_t)eBase * 64);
            #pragma unroll
            for (int r = 0; r < 8; r++) {
                int f = r * 32 + lane, e = f >> 4, i4 = f & 15;
                float4 q = src[f];
                __half2 h01 = __floats2half2_rn(q.x, q.y), h23 = __floats2half2_rn(q.z, q.w);
                float2 g01 = __half22float2(h01), g23 = __half22float2(h23);
                __half2 l01 = __floats2half2_rn(q.x - g01.x, q.y - g01.y);
                __half2 l23 = __floats2half2_rn(q.z - g23.x, q.w - g23.y);
                ((uint2*)invH)[e * 18 + i4] =
                    make_uint2(*(uint32_t*)&h01, *(uint32_t*)&h23);
                ((uint2*)invL)[e * 18 + i4] =
                    make_uint2(*(uint32_t*)&l01, *(uint32_t*)&l23);
            }
        }
        // ---- SH (lanes 0..15, one edge each) ----
        if (lane < 16) {
            const float* vp = edge_vec + (size_t)(eBase + lane) * 3;
            float vx = vp[0], vy = vp[1], vz = vp[2];
            float rn = rsqrtf(vx * vx + vy * vy + vz * vz);
            float x = vx * rn, y = vy * rn, z = vz * rn;
            shs4[lane * 2 + 0] = make_float4(SQ3f * x, SQ3f * y, SQ3f * z, SQ15f * x * z);
            shs4[lane * 2 + 1] = make_float4(SQ15f * x * y,
                                             SQ5f * (y * y - 0.5f * (x * x + z * z)),
                                             SQ15f * y * z,
                                             (HSQ3f * SQ5f) * (z * z - x * x));
        }
        __syncwarp();

        // ---- A fragments (all 4 k-chunks, hi+lo) into registers ----
        uint32_t Ah[16], Al[16];
        #pragma unroll
        for (int kc = 0; kc < 4; kc++) {
            int b = kc * 8 + t;
            Ah[kc*4+0] = invH[g * 36 + b];       Ah[kc*4+1] = invH[(g + 8) * 36 + b];
            Ah[kc*4+2] = invH[g * 36 + b + 4];   Ah[kc*4+3] = invH[(g + 8) * 36 + b + 4];
            Al[kc*4+0] = invL[g * 36 + b];       Al[kc*4+1] = invL[(g + 8) * 36 + b];
            Al[kc*4+2] = invL[g * 36 + b + 4];   Al[kc*4+3] = invL[(g + 8) * 36 + b + 4];
        }
        __syncwarp();   // frag reads done before wS (alias) is written

        // ---- GEMM: 24 n-chunks processed in pairs (ILP), 3-term f16 split ----
        #pragma unroll 1
        for (int np = 0; np < 12; np++) {
            int n0 = np * 16, n1 = n0 + 8;
            float c0 = 0.f, c1 = 0.f, c2 = 0.f, c3 = 0.f;
            float d0 = 0.f, d1 = 0.f, d2 = 0.f, d3 = 0.f;
            #pragma unroll
            for (int kc = 0; kc < 4; kc++) {
                int bi0 = (n0 + g) * 36 + kc * 8 + t;
                int bi1 = (n1 + g) * 36 + kc * 8 + t;
                uint32_t bh0 = WhW[bi0], bh1 = WhW[bi0 + 4];
                uint32_t bl0 = WlW[bi0], bl1 = WlW[bi0 + 4];
                uint32_t ch0 = WhW[bi1], ch1 = WhW[bi1 + 4];
                uint32_t cl0 = WlW[bi1], cl1 = WlW[bi1 + 4];
                const uint32_t* ah = Ah + kc * 4;
                const uint32_t* al = Al + kc * 4;
                mma16816(c0,c1,c2,c3, ah[0],ah[1],ah[2],ah[3], bh0,bh1);
                mma16816(d0,d1,d2,d3, ah[0],ah[1],ah[2],ah[3], ch0,ch1);
                mma16816(c0,c1,c2,c3, al[0],al[1],al[2],al[3], bh0,bh1);
                mma16816(d0,d1,d2,d3, al[0],al[1],al[2],al[3], ch0,ch1);
                mma16816(c0,c1,c2,c3, ah[0],ah[1],ah[2],ah[3], bl0,bl1);
                mma16816(d0,d1,d2,d3, ah[0],ah[1],ah[2],ah[3], cl0,cl1);
            }
            *(float2*)(wS + g * 200 + n0 + 2 * t)       = make_float2(c0, c1);
            *(float2*)(wS + (g + 8) * 200 + n0 + 2 * t) = make_float2(c2, c3);
            *(float2*)(wS + g * 200 + n1 + 2 * t)       = make_float2(d0, d1);
            *(float2*)(wS + (g + 8) * 200 + n1 + 2 * t) = make_float2(d2, d3);
        }

        // ---- epilogue (R6-proven): per edge SH fan-out -> stage -> bulk store ----
        const int rot = lane >> 4;
        #pragma unroll 1
        for (int e = 0; e < T_E; ++e) {
            if (lane == 0) asm volatile("cp.async.bulk.wait_group 1;" ::: "memory");
            __syncwarp();

            float4 shA = shs4[e * 2 + 0];
            float4 shB = shs4[e * 2 + 1];
            const float2* wrow = (const float2*)(wS + e * 200) + lane * 3;
            float2 f0 = wrow[0], f1 = wrow[1], f2 = wrow[2];
            float w0x = f0.x, w1x = f0.y, w2x = f1.x;
            float w0y = f1.y, w1y = f2.x, w2y = f2.y;

            float2 pr[9];
            pr[0] = make_float2(w0x,         shA.x * w1x);
            pr[1] = make_float2(shA.y * w1x, shA.z * w1x);
            pr[2] = make_float2(shA.w * w2x, shB.x * w2x);
            pr[3] = make_float2(shB.y * w2x, shB.z * w2x);
            pr[4] = make_float2(shB.w * w2x, w0y);
            pr[5] = make_float2(shA.x * w1y, shA.y * w1y);
            pr[6] = make_float2(shA.z * w1y, shA.w * w2y);
            pr[7] = make_float2(shB.x * w2y, shB.y * w2y);
            pr[8] = make_float2(shB.z * w2y, shB.w * w2y);

            float2* sp = (float2*)(stg + (e & 1) * STG_SLOT) + lane * 9;
            #pragma unroll
            for (int m = 0; m < 9; m++) {
                const int k = (m + 1) % 9;
                float2 v = rot ? pr[k] : pr[m];
                int    o = rot ? k     : m;
                sp[o] = v;
            }
            __syncwarp();

            if (lane == 0) {
                asm volatile("fence.proxy.async.shared::cta;" ::: "memory");
                asm volatile("cp.async.bulk.global.shared::cta.bulk_group [%0], [%1], %2;"
                             :: "l"(out + (size_t)(eBase + e) * 576),
                                "r"(stgAddr + (uint32_t)((e & 1) * STG_SLOT)),
                                "n"(STG_SLOT) : "memory");
                asm volatile("cp.async.bulk.commit_group;" ::: "memory");
            }
        }
    }

    if (lane == 0) asm volatile("cp.async.bulk.wait_group 0;" ::: "memory");
    __syncwarp();
}

extern "C" void kernel_launch(void* const* d_in, const int* in_sizes, int n_in,
                              void* d_out, int out_size) {
    const float* edge_vec = (const float*)d_in[0];   // [E, 3]
    const float* inv      = (const float*)d_in[1];   // [E, 64]
    const float* W        = (const float*)d_in[2];   // [64, 192]
    float* out            = (float*)d_out;           // [E, 64, 9]
    (void)in_sizes; (void)n_in; (void)out_size;

    int sms = 148;
    cudaDeviceGetAttribute(&sms, cudaDevAttrMultiProcessorCount, 0);
    cudaFuncSetAttribute(sh_embed_hmma,
                         cudaFuncAttributeMaxDynamicSharedMemorySize, SMEM_BYTES);
    sh_embed_hmma<<<sms, 256, SMEM_BYTES>>>(edge_vec, inv, W, out);
}